// round 2
// baseline (speedup 1.0000x reference)
#include <cuda_runtime.h>
#include <math.h>

#define T_TOK 8192
#define H_DIM 1024
#define E_NUM 8
#define I_DIM 2048

// ---------------- scratch (device globals; no allocations allowed) ----------
__device__ int   d_cnt[E_NUM];
__device__ float d_psum[E_NUM];
__device__ int   d_off[E_NUM];
__device__ int   d_tok[E_NUM * T_TOK];
__device__ float d_cw [E_NUM * T_TOK];
__device__ float d_hidden[(size_t)T_TOK * 2 * I_DIM];   // 134 MB, compact slots

// ---------------- zero counters (graph-replay safe) -------------------------
__global__ void zero_kernel() {
    int i = threadIdx.x;
    if (i < E_NUM) { d_cnt[i] = 0; d_psum[i] = 0.f; }
}

// ---------------- gating: logits -> softmax -> top2 -> lists ----------------
// one warp per token; 8 warps (256 threads) per block
__global__ void gate_kernel(const float* __restrict__ x,
                            const float* __restrict__ gw) {
    int tok  = (blockIdx.x * blockDim.x + threadIdx.x) >> 5;
    int lane = threadIdx.x & 31;
    int wib  = threadIdx.x >> 5;

    __shared__ float sprob[8][E_NUM];

    float acc[E_NUM];
#pragma unroll
    for (int e = 0; e < E_NUM; e++) acc[e] = 0.f;

    const float* xr = x + (size_t)tok * H_DIM;
    for (int h = lane; h < H_DIM; h += 32) {
        float xv = xr[h];
#pragma unroll
        for (int e = 0; e < E_NUM; e++)
            acc[e] = fmaf(xv, gw[e * H_DIM + h], acc[e]);
    }
#pragma unroll
    for (int e = 0; e < E_NUM; e++) {
#pragma unroll
        for (int o = 16; o > 0; o >>= 1)
            acc[e] += __shfl_xor_sync(0xffffffffu, acc[e], o);
    }

    if (lane == 0) {
        float mx = acc[0];
#pragma unroll
        for (int e = 1; e < E_NUM; e++) mx = fmaxf(mx, acc[e]);
        float p[E_NUM], s = 0.f;
#pragma unroll
        for (int e = 0; e < E_NUM; e++) { p[e] = expf(acc[e] - mx); s += p[e]; }
        float inv = 1.f / s;
#pragma unroll
        for (int e = 0; e < E_NUM; e++) { p[e] *= inv; sprob[wib][e] = p[e]; }

        // top-2, jax tie rule: strict greater keeps lowest index
        int i0 = 0; float v0 = p[0];
#pragma unroll
        for (int e = 1; e < E_NUM; e++) if (p[e] > v0) { v0 = p[e]; i0 = e; }
        int i1 = -1; float v1 = -1.f;
#pragma unroll
        for (int e = 0; e < E_NUM; e++)
            if (e != i0 && p[e] > v1) { v1 = p[e]; i1 = e; }

        float wn  = 1.f / (v0 + v1 + 1e-6f);
        float cw0 = v0 * wn, cw1 = v1 * wn;

        int p0 = atomicAdd(&d_cnt[i0], 1);
        d_tok[i0 * T_TOK + p0] = tok;  d_cw[i0 * T_TOK + p0] = cw0;
        int p1 = atomicAdd(&d_cnt[i1], 1);
        d_tok[i1 * T_TOK + p1] = tok;  d_cw[i1 * T_TOK + p1] = cw1;
    }
    __syncthreads();
    if (threadIdx.x < E_NUM) {
        float s = 0.f;
#pragma unroll
        for (int w = 0; w < 8; w++) s += sprob[w][threadIdx.x];
        atomicAdd(&d_psum[threadIdx.x], s);
    }
}

// ---------------- offsets + aux loss ----------------------------------------
__global__ void offsets_kernel(float* out, int out_size) {
    if (threadIdx.x == 0) {
        int off = 0;
        float aux = 0.f;
        for (int e = 0; e < E_NUM; e++) {
            d_off[e] = off;
            off += d_cnt[e];
            aux += ((float)d_cnt[e] / (float)T_TOK) * (d_psum[e] / (float)T_TOK);
        }
        aux *= (float)E_NUM;
        if (out_size > T_TOK * H_DIM) out[T_TOK * H_DIM] = aux;
    }
}

// ---------------- FFN part 1: hidden = silu(X W1^T) * (X W3^T) --------------
// per-expert gathered GEMM; tile 128(M) x 64(N), BK=8, 256 thr, 8x4 micro x2
__global__ void __launch_bounds__(256, 2)
ffn1_kernel(const float* __restrict__ x,
            const float* __restrict__ w1,
            const float* __restrict__ w3) {
    int e   = blockIdx.z;
    int cnt = d_cnt[e];
    int m0  = blockIdx.y * 128;
    if (m0 >= cnt) return;
    int n0  = blockIdx.x * 64;

    __shared__ float As [8][128];
    __shared__ float B1s[8][64];
    __shared__ float B3s[8][64];

    int tid = threadIdx.x;
    int tx = tid & 15, ty = tid >> 4;

    // global-load assignments
    int aRow = tid >> 1;               // 0..127
    int aCol = (tid & 1) << 2;         // 0 or 4
    int m    = m0 + aRow;
    bool aValid = (m < cnt);
    int tokA = aValid ? d_tok[e * T_TOK + m] : 0;
    const float* aPtr = x + (size_t)tokA * H_DIM + aCol;

    int bRow = (tid & 127) >> 1;       // 0..63
    int bCol = (tid & 1) << 2;
    const float* wsel = (tid < 128) ? w1 : w3;
    const float* bPtr = wsel + ((size_t)e * I_DIM + n0 + bRow) * H_DIM + bCol;

    float acc1[8][4], acc3[8][4];
#pragma unroll
    for (int r = 0; r < 8; r++)
#pragma unroll
        for (int c = 0; c < 4; c++) { acc1[r][c] = 0.f; acc3[r][c] = 0.f; }

    for (int k0 = 0; k0 < H_DIM; k0 += 8) {
        float4 av = aValid ? *(const float4*)(aPtr + k0)
                           : make_float4(0.f, 0.f, 0.f, 0.f);
        float4 bv = *(const float4*)(bPtr + k0);
        __syncthreads();
        As[aCol + 0][aRow] = av.x; As[aCol + 1][aRow] = av.y;
        As[aCol + 2][aRow] = av.z; As[aCol + 3][aRow] = av.w;
        if (tid < 128) {
            B1s[bCol + 0][bRow] = bv.x; B1s[bCol + 1][bRow] = bv.y;
            B1s[bCol + 2][bRow] = bv.z; B1s[bCol + 3][bRow] = bv.w;
        } else {
            B3s[bCol + 0][bRow] = bv.x; B3s[bCol + 1][bRow] = bv.y;
            B3s[bCol + 2][bRow] = bv.z; B3s[bCol + 3][bRow] = bv.w;
        }
        __syncthreads();
#pragma unroll
        for (int kk = 0; kk < 8; kk++) {
            float4 a0 = *(const float4*)&As[kk][ty * 8];
            float4 a1 = *(const float4*)&As[kk][ty * 8 + 4];
            float4 b1 = *(const float4*)&B1s[kk][tx * 4];
            float4 b3 = *(const float4*)&B3s[kk][tx * 4];
            float a[8] = {a0.x, a0.y, a0.z, a0.w, a1.x, a1.y, a1.z, a1.w};
            float v1[4] = {b1.x, b1.y, b1.z, b1.w};
            float v3[4] = {b3.x, b3.y, b3.z, b3.w};
#pragma unroll
            for (int r = 0; r < 8; r++)
#pragma unroll
                for (int c = 0; c < 4; c++) {
                    acc1[r][c] = fmaf(a[r], v1[c], acc1[r][c]);
                    acc3[r][c] = fmaf(a[r], v3[c], acc3[r][c]);
                }
        }
    }

    int base = d_off[e];
#pragma unroll
    for (int r = 0; r < 8; r++) {
        int mm = m0 + ty * 8 + r;
        if (mm < cnt) {
            float* hrow = d_hidden + ((size_t)(base + mm)) * I_DIM + n0 + tx * 4;
            float4 hv;
            float g;
            g = acc1[r][0]; hv.x = (g / (1.f + expf(-g))) * acc3[r][0];
            g = acc1[r][1]; hv.y = (g / (1.f + expf(-g))) * acc3[r][1];
            g = acc1[r][2]; hv.z = (g / (1.f + expf(-g))) * acc3[r][2];
            g = acc1[r][3]; hv.w = (g / (1.f + expf(-g))) * acc3[r][3];
            *(float4*)hrow = hv;
        }
    }
}

// ---------------- FFN part 2: out[tok] += cw * (hidden W2^T) ----------------
__global__ void __launch_bounds__(256, 2)
ffn2_kernel(const float* __restrict__ w2, float* __restrict__ out) {
    int e   = blockIdx.z;
    int cnt = d_cnt[e];
    int m0  = blockIdx.y * 128;
    if (m0 >= cnt) return;
    int n0  = blockIdx.x * 64;
    int base = d_off[e];

    __shared__ float As[8][128];
    __shared__ float Bs[8][64];

    int tid = threadIdx.x;
    int tx = tid & 15, ty = tid >> 4;

    int aRow = tid >> 1;
    int aCol = (tid & 1) << 2;
    int m    = m0 + aRow;
    bool aValid = (m < cnt);
    const float* aPtr = d_hidden + (size_t)(base + (aValid ? m : 0)) * I_DIM + aCol;

    int bRow = (tid & 127) >> 1;
    int bCol = (tid & 1) << 2;
    const float* bPtr = w2 + ((size_t)e * H_DIM + n0 + bRow) * I_DIM + bCol;

    float acc[8][4];
#pragma unroll
    for (int r = 0; r < 8; r++)
#pragma unroll
        for (int c = 0; c < 4; c++) acc[r][c] = 0.f;

    for (int k0 = 0; k0 < I_DIM; k0 += 8) {
        float4 av = aValid ? *(const float4*)(aPtr + k0)
                           : make_float4(0.f, 0.f, 0.f, 0.f);
        float4 bv;
        if (tid < 128) bv = *(const float4*)(bPtr + k0);
        __syncthreads();
        As[aCol + 0][aRow] = av.x; As[aCol + 1][aRow] = av.y;
        As[aCol + 2][aRow] = av.z; As[aCol + 3][aRow] = av.w;
        if (tid < 128) {
            Bs[bCol + 0][bRow] = bv.x; Bs[bCol + 1][bRow] = bv.y;
            Bs[bCol + 2][bRow] = bv.z; Bs[bCol + 3][bRow] = bv.w;
        }
        __syncthreads();
#pragma unroll
        for (int kk = 0; kk < 8; kk++) {
            float4 a0 = *(const float4*)&As[kk][ty * 8];
            float4 a1 = *(const float4*)&As[kk][ty * 8 + 4];
            float4 b  = *(const float4*)&Bs[kk][tx * 4];
            float a[8] = {a0.x, a0.y, a0.z, a0.w, a1.x, a1.y, a1.z, a1.w};
            float v[4] = {b.x, b.y, b.z, b.w};
#pragma unroll
            for (int r = 0; r < 8; r++)
#pragma unroll
                for (int c = 0; c < 4; c++)
                    acc[r][c] = fmaf(a[r], v[c], acc[r][c]);
        }
    }

#pragma unroll
    for (int r = 0; r < 8; r++) {
        int mm = m0 + ty * 8 + r;
        if (mm < cnt) {
            int tok  = d_tok[e * T_TOK + mm];
            float cw = d_cw [e * T_TOK + mm];
            float* orow = out + (size_t)tok * H_DIM + n0 + tx * 4;
#pragma unroll
            for (int c = 0; c < 4; c++)
                atomicAdd(&orow[c], cw * acc[r][c]);
        }
    }
}

// ---------------- launch -----------------------------------------------------
extern "C" void kernel_launch(void* const* d_in, const int* in_sizes, int n_in,
                              void* d_out, int out_size) {
    const float* x    = (const float*)d_in[0];
    const float* gw   = (const float*)d_in[1];
    const float* w1   = (const float*)d_in[2];
    const float* w2   = (const float*)d_in[3];
    const float* w3   = (const float*)d_in[4];
    float* out = (float*)d_out;

    cudaMemsetAsync(d_out, 0, (size_t)out_size * sizeof(float), 0);
    zero_kernel<<<1, 32>>>();
    gate_kernel<<<T_TOK / 8, 256>>>(x, gw);
    offsets_kernel<<<1, 32>>>(out, out_size);
    ffn1_kernel<<<dim3(I_DIM / 64, T_TOK / 128, E_NUM), 256>>>(x, w1, w3);
    ffn2_kernel<<<dim3(H_DIM / 64, T_TOK / 128, E_NUM), 256>>>(w2, out);
}

// round 4
// speedup vs baseline: 2.4538x; 2.4538x over previous
#include <cuda_runtime.h>
#include <cuda_bf16.h>
#include <math.h>
#include <stdint.h>

#define T_TOK 8192
#define H_DIM 1024
#define E_NUM 8
#define I_DIM 2048
#define NROW  (T_TOK * 2)

// ---------------- device-global scratch -------------------------------------
__device__ int   d_cnt[E_NUM];
__device__ float d_psum[E_NUM];
__device__ int   d_off[E_NUM];
__device__ int   d_tok[E_NUM * T_TOK];
__device__ float d_cw [E_NUM * T_TOK];
__device__ int   d_slot[T_TOK * 2];

__device__ __nv_bfloat16 g_xhi[(size_t)T_TOK * H_DIM];
__device__ __nv_bfloat16 g_xlo[(size_t)T_TOK * H_DIM];
__device__ __nv_bfloat16 g_w1hi[(size_t)E_NUM * I_DIM * H_DIM];
__device__ __nv_bfloat16 g_w1lo[(size_t)E_NUM * I_DIM * H_DIM];
__device__ __nv_bfloat16 g_w3hi[(size_t)E_NUM * I_DIM * H_DIM];
__device__ __nv_bfloat16 g_w3lo[(size_t)E_NUM * I_DIM * H_DIM];
__device__ __nv_bfloat16 g_w2hi[(size_t)E_NUM * H_DIM * I_DIM];
__device__ __nv_bfloat16 g_w2lo[(size_t)E_NUM * H_DIM * I_DIM];
__device__ __nv_bfloat16 g_hidhi[(size_t)NROW * I_DIM];
__device__ __nv_bfloat16 g_hidlo[(size_t)NROW * I_DIM];
__device__ float         g_y[(size_t)NROW * H_DIM];

// ---------------- PTX helpers (baseline ISA only) ----------------------------
__device__ __forceinline__ uint32_t smem_u32(const void* p) {
    uint32_t r;
    asm("{ .reg .u64 t; cvta.to.shared.u64 t, %1; cvt.u32.u64 %0, t; }"
        : "=r"(r) : "l"(p));
    return r;
}
__device__ __forceinline__ void cp16(uint32_t saddr, const void* gaddr) {
    asm volatile("cp.async.cg.shared.global [%0], [%1], 16;"
                 :: "r"(saddr), "l"(gaddr));
}
__device__ __forceinline__ void cp_commit() {
    asm volatile("cp.async.commit_group;");
}
template <int N> __device__ __forceinline__ void cp_wait() {
    asm volatile("cp.async.wait_group %0;" :: "n"(N));
}
__device__ __forceinline__ void ldsm4(uint32_t* r, uint32_t addr) {
    asm volatile("ldmatrix.sync.aligned.m8n8.x4.shared.b16 {%0,%1,%2,%3}, [%4];"
                 : "=r"(r[0]), "=r"(r[1]), "=r"(r[2]), "=r"(r[3]) : "r"(addr));
}
__device__ __forceinline__ void mma16816(float* d, const uint32_t* a,
                                         const uint32_t* b) {
    asm volatile(
        "mma.sync.aligned.m16n8k16.row.col.f32.bf16.bf16.f32 "
        "{%0,%1,%2,%3}, {%4,%5,%6,%7}, {%8,%9}, {%0,%1,%2,%3};"
        : "+f"(d[0]), "+f"(d[1]), "+f"(d[2]), "+f"(d[3])
        : "r"(a[0]), "r"(a[1]), "r"(a[2]), "r"(a[3]), "r"(b[0]), "r"(b[1]));
}
// swizzled address inside a [128 rows][64B] tile: conflict-free for ldmatrix+STS
__device__ __forceinline__ uint32_t tile_addr(uint32_t base, int row, int chunk) {
    return base + row * 64 + ((chunk ^ ((row >> 1) & 3)) << 4);
}
__device__ __forceinline__ uint32_t pack_bf2(__nv_bfloat16 a, __nv_bfloat16 b) {
    __nv_bfloat162 t = __halves2bfloat162(a, b);
    return *reinterpret_cast<uint32_t*>(&t);
}

// ---------------- small kernels ----------------------------------------------
__global__ void zero_kernel() {
    int i = threadIdx.x;
    if (i < E_NUM) { d_cnt[i] = 0; d_psum[i] = 0.f; }
}

__global__ void split_kernel(const float* __restrict__ src, int which, int n) {
    __nv_bfloat16 *hi, *lo;
    switch (which) {
        case 0: hi = g_xhi;  lo = g_xlo;  break;
        case 1: hi = g_w1hi; lo = g_w1lo; break;
        case 2: hi = g_w2hi; lo = g_w2lo; break;
        default: hi = g_w3hi; lo = g_w3lo; break;
    }
    int i = (blockIdx.x * blockDim.x + threadIdx.x) * 4;
    if (i >= n) return;
    float4 v = *(const float4*)(src + i);
    __nv_bfloat16 hx = __float2bfloat16(v.x), hy = __float2bfloat16(v.y);
    __nv_bfloat16 hz = __float2bfloat16(v.z), hw = __float2bfloat16(v.w);
    __nv_bfloat16 lx = __float2bfloat16(v.x - __bfloat162float(hx));
    __nv_bfloat16 ly = __float2bfloat16(v.y - __bfloat162float(hy));
    __nv_bfloat16 lz = __float2bfloat16(v.z - __bfloat162float(hz));
    __nv_bfloat16 lw = __float2bfloat16(v.w - __bfloat162float(hw));
    uint2 H, L;
    H.x = pack_bf2(hx, hy); H.y = pack_bf2(hz, hw);
    L.x = pack_bf2(lx, ly); L.y = pack_bf2(lz, lw);
    *(uint2*)(hi + i) = H;
    *(uint2*)(lo + i) = L;
}

__global__ void gate_kernel(const float* __restrict__ x,
                            const float* __restrict__ gw) {
    int tok  = (blockIdx.x * blockDim.x + threadIdx.x) >> 5;
    int lane = threadIdx.x & 31;
    int wib  = threadIdx.x >> 5;
    __shared__ float sprob[8][E_NUM];

    float acc[E_NUM];
#pragma unroll
    for (int e = 0; e < E_NUM; e++) acc[e] = 0.f;
    const float* xr = x + (size_t)tok * H_DIM;
    for (int h = lane; h < H_DIM; h += 32) {
        float xv = xr[h];
#pragma unroll
        for (int e = 0; e < E_NUM; e++)
            acc[e] = fmaf(xv, gw[e * H_DIM + h], acc[e]);
    }
#pragma unroll
    for (int e = 0; e < E_NUM; e++)
#pragma unroll
        for (int o = 16; o > 0; o >>= 1)
            acc[e] += __shfl_xor_sync(0xffffffffu, acc[e], o);

    if (lane == 0) {
        float mx = acc[0];
#pragma unroll
        for (int e = 1; e < E_NUM; e++) mx = fmaxf(mx, acc[e]);
        float p[E_NUM], s = 0.f;
#pragma unroll
        for (int e = 0; e < E_NUM; e++) { p[e] = expf(acc[e] - mx); s += p[e]; }
        float inv = 1.f / s;
#pragma unroll
        for (int e = 0; e < E_NUM; e++) { p[e] *= inv; sprob[wib][e] = p[e]; }

        int i0 = 0; float v0 = p[0];
#pragma unroll
        for (int e = 1; e < E_NUM; e++) if (p[e] > v0) { v0 = p[e]; i0 = e; }
        int i1 = -1; float v1 = -1.f;
#pragma unroll
        for (int e = 0; e < E_NUM; e++)
            if (e != i0 && p[e] > v1) { v1 = p[e]; i1 = e; }

        float wn  = 1.f / (v0 + v1 + 1e-6f);
        int p0 = atomicAdd(&d_cnt[i0], 1);
        d_tok[i0 * T_TOK + p0] = tok;  d_cw[i0 * T_TOK + p0] = v0 * wn;
        d_slot[tok * 2 + 0] = i0 * T_TOK + p0;
        int p1 = atomicAdd(&d_cnt[i1], 1);
        d_tok[i1 * T_TOK + p1] = tok;  d_cw[i1 * T_TOK + p1] = v1 * wn;
        d_slot[tok * 2 + 1] = i1 * T_TOK + p1;
    }
    __syncthreads();
    if (threadIdx.x < E_NUM) {
        float s = 0.f;
#pragma unroll
        for (int w = 0; w < 8; w++) s += sprob[w][threadIdx.x];
        atomicAdd(&d_psum[threadIdx.x], s);
    }
}

__global__ void offsets_kernel(float* out, int out_size) {
    if (threadIdx.x == 0) {
        int off = 0; float aux = 0.f;
        for (int e = 0; e < E_NUM; e++) {
            d_off[e] = off;
            off += d_cnt[e];
            aux += ((float)d_cnt[e] / (float)T_TOK) * (d_psum[e] / (float)T_TOK);
        }
        aux *= (float)E_NUM;
        if (out_size > T_TOK * H_DIM) out[T_TOK * H_DIM] = aux;
    }
}

// ---------------- GEMM tile constants ----------------------------------------
// stage layout (per stage, 32 KB): Ah[128][64B] Al Bh Bl
#define TS_AH 0
#define TS_AL 8192
#define TS_BH 16384
#define TS_BL 24576
#define STAGE 32768
#define EPI_STRIDE 68
#define F1_SMEM (2 * 128 * EPI_STRIDE * 4)   // 69632 > 2*STAGE
#define F2_SMEM (2 * STAGE)

// ---------------- FFN1: h = silu(x w1^T) * (x w3^T) --------------------------
// block tile: M=128 (routed rows), N=64 intermediate cols, both w1 & w3.
// B smem rows 0-63 = w1[n0..], 64-127 = w3[n0..]. 8 warps: (wM 0-1) x (wN 0-3);
// wN 0-1 -> gate (w1), wN 2-3 -> up (w3).
__global__ void __launch_bounds__(256, 1)
ffn1_kernel() {
    extern __shared__ char smem[];
    __shared__ int stok[128];
    const int e   = blockIdx.z;
    const int cnt = d_cnt[e];
    const int m0  = blockIdx.y * 128;
    if (m0 >= cnt) return;
    const int n0  = blockIdx.x * 64;

    const uint32_t sb = smem_u32(smem);
    const int tid = threadIdx.x, lane = tid & 31, wid = tid >> 5;
    const int wM = wid >> 2, wN = wid & 3;

    if (tid < 128) stok[tid] = (m0 + tid < cnt) ? d_tok[e * T_TOK + m0 + tid] : 0;
    __syncthreads();

    const __nv_bfloat16* bh_src[2] = {g_w1hi, g_w3hi};
    const __nv_bfloat16* bl_src[2] = {g_w1lo, g_w3lo};

    auto load_stage = [&](int k, int s) {
        const int k0 = k * 32;
        const uint32_t st = sb + s * STAGE;
#pragma unroll
        for (int t = 0; t < 8; t++) {
            int i = tid + t * 256;
            int region = i >> 9;          // 0 Ah, 1 Al, 2 Bh, 3 Bl
            int idx = i & 511;
            int row = idx >> 2, c = idx & 3;
            uint32_t dst = tile_addr(st + region * 8192, row, c);
            if (region < 2) {
                const __nv_bfloat16* src = region ? g_xlo : g_xhi;
                cp16(dst, src + (size_t)stok[row] * H_DIM + k0 + c * 8);
            } else {
                int half = row >> 6;      // 0: w1, 1: w3
                int r = row & 63;
                const __nv_bfloat16* src =
                    (region == 2) ? bh_src[half] : bl_src[half];
                cp16(dst, src + ((size_t)e * I_DIM + n0 + r) * H_DIM + k0 + c * 8);
            }
        }
        cp_commit();
    };

    float acc[4][4][4];
#pragma unroll
    for (int mt = 0; mt < 4; mt++)
#pragma unroll
        for (int nt = 0; nt < 4; nt++)
#pragma unroll
            for (int q = 0; q < 4; q++) acc[mt][nt][q] = 0.f;

    const int NK = H_DIM / 32;
    load_stage(0, 0);

    for (int k = 0; k < NK; k++) {
        const int s = k & 1;
        if (k + 1 < NK) { load_stage(k + 1, s ^ 1); cp_wait<1>(); }
        else            { cp_wait<0>(); }
        __syncthreads();

        const uint32_t st = sb + s * STAGE;
#pragma unroll
        for (int ks = 0; ks < 2; ks++) {
            const int cb = ks * 2 + (lane >> 4);
            uint32_t ah[4][4], al[4][4], bh[2][4], bl[2][4];
#pragma unroll
            for (int mt = 0; mt < 4; mt++) {
                int row = wM * 64 + mt * 16 + (lane & 15);
                ldsm4(ah[mt], tile_addr(st + TS_AH, row, cb));
                ldsm4(al[mt], tile_addr(st + TS_AL, row, cb));
            }
#pragma unroll
            for (int p = 0; p < 2; p++) {
                int row = wN * 32 + p * 16 + (lane & 15);
                ldsm4(bh[p], tile_addr(st + TS_BH, row, cb));
                ldsm4(bl[p], tile_addr(st + TS_BL, row, cb));
            }
#pragma unroll
            for (int mt = 0; mt < 4; mt++)
#pragma unroll
                for (int nt = 0; nt < 4; nt++) {
                    int p = nt >> 1, o = nt & 1;
                    uint32_t bfh[2] = {bh[p][o], bh[p][o + 2]};
                    uint32_t bfl[2] = {bl[p][o], bl[p][o + 2]};
                    mma16816(acc[mt][nt], ah[mt], bfh);
                    mma16816(acc[mt][nt], ah[mt], bfl);
                    mma16816(acc[mt][nt], al[mt], bfh);
                }
        }
        __syncthreads();
    }

    // epilogue: stash g/u in smem, combine, split to bf16 hi/lo
    float* Sg = (float*)smem;
    float* Su = Sg + 128 * EPI_STRIDE;
    float* Sacc = (wN < 2) ? Sg : Su;
    const int ncb = (wN & 1) * 32;
#pragma unroll
    for (int mt = 0; mt < 4; mt++) {
        int row = wM * 64 + mt * 16 + (lane >> 2);
#pragma unroll
        for (int nt = 0; nt < 4; nt++) {
            int col = ncb + nt * 8 + (lane & 3) * 2;
            Sacc[row * EPI_STRIDE + col]     = acc[mt][nt][0];
            Sacc[row * EPI_STRIDE + col + 1] = acc[mt][nt][1];
            Sacc[(row + 8) * EPI_STRIDE + col]     = acc[mt][nt][2];
            Sacc[(row + 8) * EPI_STRIDE + col + 1] = acc[mt][nt][3];
        }
    }
    __syncthreads();

    const int base = d_off[e];
    for (int idx = tid; idx < 128 * 32; idx += 256) {
        int m = idx >> 5;
        if (m0 + m >= cnt) continue;
        int c = (idx & 31) * 2;
        float g0 = Sg[m * EPI_STRIDE + c], g1 = Sg[m * EPI_STRIDE + c + 1];
        float u0 = Su[m * EPI_STRIDE + c], u1 = Su[m * EPI_STRIDE + c + 1];
        float h0 = (g0 / (1.f + expf(-g0))) * u0;
        float h1 = (g1 / (1.f + expf(-g1))) * u1;
        __nv_bfloat16 h0b = __float2bfloat16(h0);
        __nv_bfloat16 h1b = __float2bfloat16(h1);
        __nv_bfloat16 l0b = __float2bfloat16(h0 - __bfloat162float(h0b));
        __nv_bfloat16 l1b = __float2bfloat16(h1 - __bfloat162float(h1b));
        size_t gi = (size_t)(base + m0 + m) * I_DIM + n0 + c;
        *(uint32_t*)(g_hidhi + gi) = pack_bf2(h0b, h1b);
        *(uint32_t*)(g_hidlo + gi) = pack_bf2(l0b, l1b);
    }
}

// ---------------- FFN2: y[slot] = cw * (hidden w2^T) -------------------------
// block tile M=128, N=128 (H cols). 8 warps (wM 0-1) x (wN 0-3), 64x32 each.
__global__ void __launch_bounds__(256, 1)
ffn2_kernel() {
    extern __shared__ char smem[];
    __shared__ float scw[128];
    const int e   = blockIdx.z;
    const int cnt = d_cnt[e];
    const int m0  = blockIdx.y * 128;
    if (m0 >= cnt) return;
    const int n0  = blockIdx.x * 128;
    const int base = d_off[e];

    const uint32_t sb = smem_u32(smem);
    const int tid = threadIdx.x, lane = tid & 31, wid = tid >> 5;
    const int wM = wid >> 2, wN = wid & 3;

    if (tid < 128)
        scw[tid] = (m0 + tid < cnt) ? d_cw[e * T_TOK + m0 + tid] : 0.f;
    __syncthreads();

    auto load_stage = [&](int k, int s) {
        const int k0 = k * 32;
        const uint32_t st = sb + s * STAGE;
#pragma unroll
        for (int t = 0; t < 8; t++) {
            int i = tid + t * 256;
            int region = i >> 9;
            int idx = i & 511;
            int row = idx >> 2, c = idx & 3;
            uint32_t dst = tile_addr(st + region * 8192, row, c);
            if (region < 2) {
                const __nv_bfloat16* src = region ? g_hidlo : g_hidhi;
                int m = m0 + row;
                size_t gr = (size_t)(base + ((m < cnt) ? m : 0));
                cp16(dst, src + gr * I_DIM + k0 + c * 8);
            } else {
                const __nv_bfloat16* src = (region == 2) ? g_w2hi : g_w2lo;
                cp16(dst, src + ((size_t)e * H_DIM + n0 + row) * I_DIM + k0 + c * 8);
            }
        }
        cp_commit();
    };

    float acc[4][4][4];
#pragma unroll
    for (int mt = 0; mt < 4; mt++)
#pragma unroll
        for (int nt = 0; nt < 4; nt++)
#pragma unroll
            for (int q = 0; q < 4; q++) acc[mt][nt][q] = 0.f;

    const int NK = I_DIM / 32;
    load_stage(0, 0);

    for (int k = 0; k < NK; k++) {
        const int s = k & 1;
        if (k + 1 < NK) { load_stage(k + 1, s ^ 1); cp_wait<1>(); }
        else            { cp_wait<0>(); }
        __syncthreads();

        const uint32_t st = sb + s * STAGE;
#pragma unroll
        for (int ks = 0; ks < 2; ks++) {
            const int cb = ks * 2 + (lane >> 4);
            uint32_t ah[4][4], al[4][4], bh[2][4], bl[2][4];
#pragma unroll
            for (int mt = 0; mt < 4; mt++) {
                int row = wM * 64 + mt * 16 + (lane & 15);
                ldsm4(ah[mt], tile_addr(st + TS_AH, row, cb));
                ldsm4(al[mt], tile_addr(st + TS_AL, row, cb));
            }
#pragma unroll
            for (int p = 0; p < 2; p++) {
                int row = wN * 32 + p * 16 + (lane & 15);
                ldsm4(bh[p], tile_addr(st + TS_BH, row, cb));
                ldsm4(bl[p], tile_addr(st + TS_BL, row, cb));
            }
#pragma unroll
            for (int mt = 0; mt < 4; mt++)
#pragma unroll
                for (int nt = 0; nt < 4; nt++) {
                    int p = nt >> 1, o = nt & 1;
                    uint32_t bfh[2] = {bh[p][o], bh[p][o + 2]};
                    uint32_t bfl[2] = {bl[p][o], bl[p][o + 2]};
                    mma16816(acc[mt][nt], ah[mt], bfh);
                    mma16816(acc[mt][nt], ah[mt], bfl);
                    mma16816(acc[mt][nt], al[mt], bfh);
                }
        }
        __syncthreads();
    }

    // epilogue: scale by cw, store f32 rows to compact y
#pragma unroll
    for (int mt = 0; mt < 4; mt++) {
        int r0 = wM * 64 + mt * 16 + (lane >> 2);
        int r1 = r0 + 8;
        bool v0 = (m0 + r0 < cnt), v1 = (m0 + r1 < cnt);
        float c0 = scw[r0], c1 = scw[r1];
        float* y0 = g_y + (size_t)(base + m0 + r0) * H_DIM + n0;
        float* y1 = g_y + (size_t)(base + m0 + r1) * H_DIM + n0;
#pragma unroll
        for (int nt = 0; nt < 4; nt++) {
            int col = wN * 32 + nt * 8 + (lane & 3) * 2;
            if (v0) *(float2*)(y0 + col) =
                make_float2(c0 * acc[mt][nt][0], c0 * acc[mt][nt][1]);
            if (v1) *(float2*)(y1 + col) =
                make_float2(c1 * acc[mt][nt][2], c1 * acc[mt][nt][3]);
        }
    }
}

// ---------------- combine ----------------------------------------------------
__global__ void combine_kernel(float* __restrict__ out) {
    const int tok = blockIdx.x;
    const int c = threadIdx.x * 4;
    int s0 = d_slot[tok * 2], s1 = d_slot[tok * 2 + 1];
    int r0 = d_off[s0 >> 13] + (s0 & (T_TOK - 1));
    int r1 = d_off[s1 >> 13] + (s1 & (T_TOK - 1));
    float4 a = *(const float4*)(g_y + (size_t)r0 * H_DIM + c);
    float4 b = *(const float4*)(g_y + (size_t)r1 * H_DIM + c);
    float4 o;
    o.x = a.x + b.x; o.y = a.y + b.y; o.z = a.z + b.z; o.w = a.w + b.w;
    *(float4*)(out + (size_t)tok * H_DIM + c) = o;
}

// ---------------- launch -----------------------------------------------------
extern "C" void kernel_launch(void* const* d_in, const int* in_sizes, int n_in,
                              void* d_out, int out_size) {
    const float* x    = (const float*)d_in[0];
    const float* gw   = (const float*)d_in[1];
    const float* w1   = (const float*)d_in[2];
    const float* w2   = (const float*)d_in[3];
    const float* w3   = (const float*)d_in[4];
    float* out = (float*)d_out;

    cudaFuncSetAttribute(ffn1_kernel, cudaFuncAttributeMaxDynamicSharedMemorySize, F1_SMEM);
    cudaFuncSetAttribute(ffn2_kernel, cudaFuncAttributeMaxDynamicSharedMemorySize, F2_SMEM);

    cudaMemsetAsync(d_out, 0, (size_t)out_size * sizeof(float), 0);
    zero_kernel<<<1, 32>>>();

    const int nx = T_TOK * H_DIM;
    const int nw = E_NUM * I_DIM * H_DIM;
    split_kernel<<<nx / 1024, 256>>>(x, 0, nx);
    split_kernel<<<nw / 1024, 256>>>(w1, 1, nw);
    split_kernel<<<nw / 1024, 256>>>(w2, 2, nw);
    split_kernel<<<nw / 1024, 256>>>(w3, 3, nw);

    gate_kernel<<<T_TOK / 8, 256>>>(x, gw);
    offsets_kernel<<<1, 32>>>(out, out_size);

    ffn1_kernel<<<dim3(I_DIM / 64, T_TOK / 128, E_NUM), 256, F1_SMEM>>>();
    ffn2_kernel<<<dim3(H_DIM / 128, T_TOK / 128, E_NUM), 256, F2_SMEM>>>();
    combine_kernel<<<T_TOK, 256>>>(out);
}

// round 5
// speedup vs baseline: 2.5148x; 1.0248x over previous
#include <cuda_runtime.h>
#include <cuda_bf16.h>
#include <math.h>
#include <stdint.h>

#define T_TOK 8192
#define H_DIM 1024
#define E_NUM 8
#define I_DIM 2048
#define NROW  (T_TOK * 2)

// ---------------- device-global scratch -------------------------------------
__device__ int   d_cnt[E_NUM];
__device__ float d_psum[E_NUM];
__device__ int   d_off[E_NUM];
__device__ int   d_tok[E_NUM * T_TOK];
__device__ float d_cw [E_NUM * T_TOK];
__device__ int   d_slot[T_TOK * 2];

__device__ __nv_bfloat16 g_xhi[(size_t)T_TOK * H_DIM];
__device__ __nv_bfloat16 g_xlo[(size_t)T_TOK * H_DIM];
__device__ __nv_bfloat16 g_w1hi[(size_t)E_NUM * I_DIM * H_DIM];
__device__ __nv_bfloat16 g_w1lo[(size_t)E_NUM * I_DIM * H_DIM];
__device__ __nv_bfloat16 g_w3hi[(size_t)E_NUM * I_DIM * H_DIM];
__device__ __nv_bfloat16 g_w3lo[(size_t)E_NUM * I_DIM * H_DIM];
__device__ __nv_bfloat16 g_w2hi[(size_t)E_NUM * H_DIM * I_DIM];
__device__ __nv_bfloat16 g_w2lo[(size_t)E_NUM * H_DIM * I_DIM];
__device__ __nv_bfloat16 g_hidhi[(size_t)NROW * I_DIM];
__device__ __nv_bfloat16 g_hidlo[(size_t)NROW * I_DIM];
__device__ float         g_y[(size_t)NROW * H_DIM];

// ---------------- PTX helpers (baseline ISA only) ----------------------------
__device__ __forceinline__ uint32_t smem_u32(const void* p) {
    uint32_t r;
    asm("{ .reg .u64 t; cvta.to.shared.u64 t, %1; cvt.u32.u64 %0, t; }"
        : "=r"(r) : "l"(p));
    return r;
}
__device__ __forceinline__ void cp16(uint32_t saddr, const void* gaddr) {
    asm volatile("cp.async.cg.shared.global [%0], [%1], 16;"
                 :: "r"(saddr), "l"(gaddr));
}
__device__ __forceinline__ void cp_commit() {
    asm volatile("cp.async.commit_group;");
}
template <int N> __device__ __forceinline__ void cp_wait() {
    asm volatile("cp.async.wait_group %0;" :: "n"(N));
}
__device__ __forceinline__ void ldsm4(uint32_t* r, uint32_t addr) {
    asm volatile("ldmatrix.sync.aligned.m8n8.x4.shared.b16 {%0,%1,%2,%3}, [%4];"
                 : "=r"(r[0]), "=r"(r[1]), "=r"(r[2]), "=r"(r[3]) : "r"(addr));
}
__device__ __forceinline__ void mma16816(float* d, const uint32_t* a,
                                         const uint32_t* b) {
    asm volatile(
        "mma.sync.aligned.m16n8k16.row.col.f32.bf16.bf16.f32 "
        "{%0,%1,%2,%3}, {%4,%5,%6,%7}, {%8,%9}, {%0,%1,%2,%3};"
        : "+f"(d[0]), "+f"(d[1]), "+f"(d[2]), "+f"(d[3])
        : "r"(a[0]), "r"(a[1]), "r"(a[2]), "r"(a[3]), "r"(b[0]), "r"(b[1]));
}
// swizzled address inside a [128 rows][64B] tile: conflict-free for ldmatrix+STS
__device__ __forceinline__ uint32_t tile_addr(uint32_t base, int row, int chunk) {
    return base + row * 64 + ((chunk ^ ((row >> 1) & 3)) << 4);
}
__device__ __forceinline__ uint32_t pack_bf2(__nv_bfloat16 a, __nv_bfloat16 b) {
    __nv_bfloat162 t = __halves2bfloat162(a, b);
    return *reinterpret_cast<uint32_t*>(&t);
}

// ---------------- small kernels ----------------------------------------------
__global__ void zero_kernel() {
    int i = threadIdx.x;
    if (i < E_NUM) { d_cnt[i] = 0; d_psum[i] = 0.f; }
}

__global__ void split_kernel(const float* __restrict__ src, int which, int n) {
    __nv_bfloat16 *hi, *lo;
    switch (which) {
        case 0: hi = g_xhi;  lo = g_xlo;  break;
        case 1: hi = g_w1hi; lo = g_w1lo; break;
        case 2: hi = g_w2hi; lo = g_w2lo; break;
        default: hi = g_w3hi; lo = g_w3lo; break;
    }
    int i = (blockIdx.x * blockDim.x + threadIdx.x) * 4;
    if (i >= n) return;
    float4 v = *(const float4*)(src + i);
    __nv_bfloat16 hx = __float2bfloat16(v.x), hy = __float2bfloat16(v.y);
    __nv_bfloat16 hz = __float2bfloat16(v.z), hw = __float2bfloat16(v.w);
    __nv_bfloat16 lx = __float2bfloat16(v.x - __bfloat162float(hx));
    __nv_bfloat16 ly = __float2bfloat16(v.y - __bfloat162float(hy));
    __nv_bfloat16 lz = __float2bfloat16(v.z - __bfloat162float(hz));
    __nv_bfloat16 lw = __float2bfloat16(v.w - __bfloat162float(hw));
    uint2 H, L;
    H.x = pack_bf2(hx, hy); H.y = pack_bf2(hz, hw);
    L.x = pack_bf2(lx, ly); L.y = pack_bf2(lz, lw);
    *(uint2*)(hi + i) = H;
    *(uint2*)(lo + i) = L;
}

__global__ void gate_kernel(const float* __restrict__ x,
                            const float* __restrict__ gw) {
    int tok  = (blockIdx.x * blockDim.x + threadIdx.x) >> 5;
    int lane = threadIdx.x & 31;
    int wib  = threadIdx.x >> 5;
    __shared__ float sprob[8][E_NUM];

    float acc[E_NUM];
#pragma unroll
    for (int e = 0; e < E_NUM; e++) acc[e] = 0.f;
    const float* xr = x + (size_t)tok * H_DIM;
    for (int h = lane; h < H_DIM; h += 32) {
        float xv = xr[h];
#pragma unroll
        for (int e = 0; e < E_NUM; e++)
            acc[e] = fmaf(xv, gw[e * H_DIM + h], acc[e]);
    }
#pragma unroll
    for (int e = 0; e < E_NUM; e++)
#pragma unroll
        for (int o = 16; o > 0; o >>= 1)
            acc[e] += __shfl_xor_sync(0xffffffffu, acc[e], o);

    if (lane == 0) {
        float mx = acc[0];
#pragma unroll
        for (int e = 1; e < E_NUM; e++) mx = fmaxf(mx, acc[e]);
        float p[E_NUM], s = 0.f;
#pragma unroll
        for (int e = 0; e < E_NUM; e++) { p[e] = expf(acc[e] - mx); s += p[e]; }
        float inv = 1.f / s;
#pragma unroll
        for (int e = 0; e < E_NUM; e++) { p[e] *= inv; sprob[wib][e] = p[e]; }

        int i0 = 0; float v0 = p[0];
#pragma unroll
        for (int e = 1; e < E_NUM; e++) if (p[e] > v0) { v0 = p[e]; i0 = e; }
        int i1 = -1; float v1 = -1.f;
#pragma unroll
        for (int e = 0; e < E_NUM; e++)
            if (e != i0 && p[e] > v1) { v1 = p[e]; i1 = e; }

        float wn  = 1.f / (v0 + v1 + 1e-6f);
        int p0 = atomicAdd(&d_cnt[i0], 1);
        d_tok[i0 * T_TOK + p0] = tok;  d_cw[i0 * T_TOK + p0] = v0 * wn;
        d_slot[tok * 2 + 0] = i0 * T_TOK + p0;
        int p1 = atomicAdd(&d_cnt[i1], 1);
        d_tok[i1 * T_TOK + p1] = tok;  d_cw[i1 * T_TOK + p1] = v1 * wn;
        d_slot[tok * 2 + 1] = i1 * T_TOK + p1;
    }
    __syncthreads();
    if (threadIdx.x < E_NUM) {
        float s = 0.f;
#pragma unroll
        for (int w = 0; w < 8; w++) s += sprob[w][threadIdx.x];
        atomicAdd(&d_psum[threadIdx.x], s);
    }
}

__global__ void offsets_kernel(float* out, int out_size) {
    if (threadIdx.x == 0) {
        int off = 0; float aux = 0.f;
        for (int e = 0; e < E_NUM; e++) {
            d_off[e] = off;
            off += d_cnt[e];
            aux += ((float)d_cnt[e] / (float)T_TOK) * (d_psum[e] / (float)T_TOK);
        }
        aux *= (float)E_NUM;
        if (out_size > T_TOK * H_DIM) out[T_TOK * H_DIM] = aux;
    }
}

// ---------------- GEMM tile constants ----------------------------------------
// stage layout (per stage, 32 KB): Ah[128][64B] Al Bh Bl. 4 stages = 128 KB.
#define TS_AH 0
#define TS_AL 8192
#define TS_BH 16384
#define TS_BL 24576
#define STAGE 32768
#define NSTAGE 4
#define EPI_STRIDE 68
#define F1_SMEM (NSTAGE * STAGE)   // 131072; epilogue (69632 B) aliases stages
#define F2_SMEM (NSTAGE * STAGE)

// ---------------- FFN1: h = silu(x w1^T) * (x w3^T) --------------------------
// block tile: M=128 routed rows, N=64 intermediate cols for both w1 & w3.
// B smem rows 0-63 = w1[n0..], 64-127 = w3[n0..]. 8 warps (wM 0-1)x(wN 0-3).
__global__ void __launch_bounds__(256, 1)
ffn1_kernel() {
    extern __shared__ char smem[];
    __shared__ int stok[128];
    const int e   = blockIdx.z;
    const int cnt = d_cnt[e];
    const int m0  = blockIdx.y * 128;
    if (m0 >= cnt) return;
    const int n0  = blockIdx.x * 64;

    const uint32_t sb = smem_u32(smem);
    const int tid = threadIdx.x, lane = tid & 31, wid = tid >> 5;
    const int wM = wid >> 2, wN = wid & 3;

    if (tid < 128) stok[tid] = (m0 + tid < cnt) ? d_tok[e * T_TOK + m0 + tid] : 0;
    __syncthreads();

    const __nv_bfloat16* bh_src[2] = {g_w1hi, g_w3hi};
    const __nv_bfloat16* bl_src[2] = {g_w1lo, g_w3lo};

    auto load_stage = [&](int k, int s) {
        const int k0 = k * 32;
        const uint32_t st = sb + s * STAGE;
#pragma unroll
        for (int t = 0; t < 8; t++) {
            int i = tid + t * 256;
            int region = i >> 9;          // 0 Ah, 1 Al, 2 Bh, 3 Bl
            int idx = i & 511;
            int row = idx >> 2, c = idx & 3;
            uint32_t dst = tile_addr(st + region * 8192, row, c);
            if (region < 2) {
                const __nv_bfloat16* src = region ? g_xlo : g_xhi;
                cp16(dst, src + (size_t)stok[row] * H_DIM + k0 + c * 8);
            } else {
                int half = row >> 6;      // 0: w1, 1: w3
                int r = row & 63;
                const __nv_bfloat16* src =
                    (region == 2) ? bh_src[half] : bl_src[half];
                cp16(dst, src + ((size_t)e * I_DIM + n0 + r) * H_DIM + k0 + c * 8);
            }
        }
    };

    float acc[4][4][4];
#pragma unroll
    for (int mt = 0; mt < 4; mt++)
#pragma unroll
        for (int nt = 0; nt < 4; nt++)
#pragma unroll
            for (int q = 0; q < 4; q++) acc[mt][nt][q] = 0.f;

    const int NK = H_DIM / 32;
    load_stage(0, 0); cp_commit();
    load_stage(1, 1); cp_commit();
    load_stage(2, 2); cp_commit();

    for (int k = 0; k < NK; k++) {
        cp_wait<2>();
        __syncthreads();
        const uint32_t st = sb + (k & 3) * STAGE;
#pragma unroll
        for (int ks = 0; ks < 2; ks++) {
            const int cb = ks * 2 + (lane >> 4);
            uint32_t ah[4][4], al[4][4], bh[2][4], bl[2][4];
#pragma unroll
            for (int mt = 0; mt < 4; mt++) {
                int row = wM * 64 + mt * 16 + (lane & 15);
                ldsm4(ah[mt], tile_addr(st + TS_AH, row, cb));
                ldsm4(al[mt], tile_addr(st + TS_AL, row, cb));
            }
#pragma unroll
            for (int p = 0; p < 2; p++) {
                int row = wN * 32 + p * 16 + (lane & 15);
                ldsm4(bh[p], tile_addr(st + TS_BH, row, cb));
                ldsm4(bl[p], tile_addr(st + TS_BL, row, cb));
            }
#pragma unroll
            for (int mt = 0; mt < 4; mt++)
#pragma unroll
                for (int nt = 0; nt < 4; nt++) {
                    int p = nt >> 1, o = nt & 1;
                    uint32_t bfh[2] = {bh[p][o], bh[p][o + 2]};
                    uint32_t bfl[2] = {bl[p][o], bl[p][o + 2]};
                    mma16816(acc[mt][nt], ah[mt], bfh);
                    mma16816(acc[mt][nt], ah[mt], bfl);
                    mma16816(acc[mt][nt], al[mt], bfh);
                }
        }
        if (k + 3 < NK) load_stage(k + 3, (k + 3) & 3);
        cp_commit();
    }
    __syncthreads();   // before epilogue aliases stage smem

    // epilogue: stash g/u in smem, combine, split to bf16 hi/lo
    float* Sg = (float*)smem;
    float* Su = Sg + 128 * EPI_STRIDE;
    float* Sacc = (wN < 2) ? Sg : Su;
    const int ncb = (wN & 1) * 32;
#pragma unroll
    for (int mt = 0; mt < 4; mt++) {
        int row = wM * 64 + mt * 16 + (lane >> 2);
#pragma unroll
        for (int nt = 0; nt < 4; nt++) {
            int col = ncb + nt * 8 + (lane & 3) * 2;
            Sacc[row * EPI_STRIDE + col]     = acc[mt][nt][0];
            Sacc[row * EPI_STRIDE + col + 1] = acc[mt][nt][1];
            Sacc[(row + 8) * EPI_STRIDE + col]     = acc[mt][nt][2];
            Sacc[(row + 8) * EPI_STRIDE + col + 1] = acc[mt][nt][3];
        }
    }
    __syncthreads();

    const int base = d_off[e];
    for (int idx = tid; idx < 128 * 32; idx += 256) {
        int m = idx >> 5;
        if (m0 + m >= cnt) continue;
        int c = (idx & 31) * 2;
        float g0 = Sg[m * EPI_STRIDE + c], g1 = Sg[m * EPI_STRIDE + c + 1];
        float u0 = Su[m * EPI_STRIDE + c], u1 = Su[m * EPI_STRIDE + c + 1];
        float h0 = (g0 / (1.f + expf(-g0))) * u0;
        float h1 = (g1 / (1.f + expf(-g1))) * u1;
        __nv_bfloat16 h0b = __float2bfloat16(h0);
        __nv_bfloat16 h1b = __float2bfloat16(h1);
        __nv_bfloat16 l0b = __float2bfloat16(h0 - __bfloat162float(h0b));
        __nv_bfloat16 l1b = __float2bfloat16(h1 - __bfloat162float(h1b));
        size_t gi = (size_t)(base + m0 + m) * I_DIM + n0 + c;
        *(uint32_t*)(g_hidhi + gi) = pack_bf2(h0b, h1b);
        *(uint32_t*)(g_hidlo + gi) = pack_bf2(l0b, l1b);
    }
}

// ---------------- FFN2: y[slot] = cw * (hidden w2^T) -------------------------
// block tile M=128, N=128 (H cols). 8 warps (wM 0-1)x(wN 0-3), 64x32 each.
__global__ void __launch_bounds__(256, 1)
ffn2_kernel() {
    extern __shared__ char smem[];
    __shared__ float scw[128];
    const int e   = blockIdx.z;
    const int cnt = d_cnt[e];
    const int m0  = blockIdx.y * 128;
    if (m0 >= cnt) return;
    const int n0  = blockIdx.x * 128;
    const int base = d_off[e];

    const uint32_t sb = smem_u32(smem);
    const int tid = threadIdx.x, lane = tid & 31, wid = tid >> 5;
    const int wM = wid >> 2, wN = wid & 3;

    if (tid < 128)
        scw[tid] = (m0 + tid < cnt) ? d_cw[e * T_TOK + m0 + tid] : 0.f;
    __syncthreads();

    auto load_stage = [&](int k, int s) {
        const int k0 = k * 32;
        const uint32_t st = sb + s * STAGE;
#pragma unroll
        for (int t = 0; t < 8; t++) {
            int i = tid + t * 256;
            int region = i >> 9;
            int idx = i & 511;
            int row = idx >> 2, c = idx & 3;
            uint32_t dst = tile_addr(st + region * 8192, row, c);
            if (region < 2) {
                const __nv_bfloat16* src = region ? g_hidlo : g_hidhi;
                int m = m0 + row;
                size_t gr = (size_t)(base + ((m < cnt) ? m : 0));
                cp16(dst, src + gr * I_DIM + k0 + c * 8);
            } else {
                const __nv_bfloat16* src = (region == 2) ? g_w2hi : g_w2lo;
                cp16(dst, src + ((size_t)e * H_DIM + n0 + row) * I_DIM + k0 + c * 8);
            }
        }
    };

    float acc[4][4][4];
#pragma unroll
    for (int mt = 0; mt < 4; mt++)
#pragma unroll
        for (int nt = 0; nt < 4; nt++)
#pragma unroll
            for (int q = 0; q < 4; q++) acc[mt][nt][q] = 0.f;

    const int NK = I_DIM / 32;
    load_stage(0, 0); cp_commit();
    load_stage(1, 1); cp_commit();
    load_stage(2, 2); cp_commit();

    for (int k = 0; k < NK; k++) {
        cp_wait<2>();
        __syncthreads();
        const uint32_t st = sb + (k & 3) * STAGE;
#pragma unroll
        for (int ks = 0; ks < 2; ks++) {
            const int cb = ks * 2 + (lane >> 4);
            uint32_t ah[4][4], al[4][4], bh[2][4], bl[2][4];
#pragma unroll
            for (int mt = 0; mt < 4; mt++) {
                int row = wM * 64 + mt * 16 + (lane & 15);
                ldsm4(ah[mt], tile_addr(st + TS_AH, row, cb));
                ldsm4(al[mt], tile_addr(st + TS_AL, row, cb));
            }
#pragma unroll
            for (int p = 0; p < 2; p++) {
                int row = wN * 32 + p * 16 + (lane & 15);
                ldsm4(bh[p], tile_addr(st + TS_BH, row, cb));
                ldsm4(bl[p], tile_addr(st + TS_BL, row, cb));
            }
#pragma unroll
            for (int mt = 0; mt < 4; mt++)
#pragma unroll
                for (int nt = 0; nt < 4; nt++) {
                    int p = nt >> 1, o = nt & 1;
                    uint32_t bfh[2] = {bh[p][o], bh[p][o + 2]};
                    uint32_t bfl[2] = {bl[p][o], bl[p][o + 2]};
                    mma16816(acc[mt][nt], ah[mt], bfh);
                    mma16816(acc[mt][nt], ah[mt], bfl);
                    mma16816(acc[mt][nt], al[mt], bfh);
                }
        }
        if (k + 3 < NK) load_stage(k + 3, (k + 3) & 3);
        cp_commit();
    }

    // epilogue: scale by cw, store f32 rows to compact y
#pragma unroll
    for (int mt = 0; mt < 4; mt++) {
        int r0 = wM * 64 + mt * 16 + (lane >> 2);
        int r1 = r0 + 8;
        bool v0 = (m0 + r0 < cnt), v1 = (m0 + r1 < cnt);
        float c0 = scw[r0], c1 = scw[r1];
        float* y0 = g_y + (size_t)(base + m0 + r0) * H_DIM + n0;
        float* y1 = g_y + (size_t)(base + m0 + r1) * H_DIM + n0;
#pragma unroll
        for (int nt = 0; nt < 4; nt++) {
            int col = wN * 32 + nt * 8 + (lane & 3) * 2;
            if (v0) *(float2*)(y0 + col) =
                make_float2(c0 * acc[mt][nt][0], c0 * acc[mt][nt][1]);
            if (v1) *(float2*)(y1 + col) =
                make_float2(c1 * acc[mt][nt][2], c1 * acc[mt][nt][3]);
        }
    }
}

// ---------------- combine ----------------------------------------------------
__global__ void combine_kernel(float* __restrict__ out) {
    const int tok = blockIdx.x;
    const int c = threadIdx.x * 4;
    int s0 = d_slot[tok * 2], s1 = d_slot[tok * 2 + 1];
    int r0 = d_off[s0 >> 13] + (s0 & (T_TOK - 1));
    int r1 = d_off[s1 >> 13] + (s1 & (T_TOK - 1));
    float4 a = *(const float4*)(g_y + (size_t)r0 * H_DIM + c);
    float4 b = *(const float4*)(g_y + (size_t)r1 * H_DIM + c);
    float4 o;
    o.x = a.x + b.x; o.y = a.y + b.y; o.z = a.z + b.z; o.w = a.w + b.w;
    *(float4*)(out + (size_t)tok * H_DIM + c) = o;
}

// ---------------- launch -----------------------------------------------------
extern "C" void kernel_launch(void* const* d_in, const int* in_sizes, int n_in,
                              void* d_out, int out_size) {
    const float* x    = (const float*)d_in[0];
    const float* gw   = (const float*)d_in[1];
    const float* w1   = (const float*)d_in[2];
    const float* w2   = (const float*)d_in[3];
    const float* w3   = (const float*)d_in[4];
    float* out = (float*)d_out;

    cudaFuncSetAttribute(ffn1_kernel, cudaFuncAttributeMaxDynamicSharedMemorySize, F1_SMEM);
    cudaFuncSetAttribute(ffn2_kernel, cudaFuncAttributeMaxDynamicSharedMemorySize, F2_SMEM);

    cudaMemsetAsync(d_out, 0, (size_t)out_size * sizeof(float), 0);
    zero_kernel<<<1, 32>>>();

    const int nx = T_TOK * H_DIM;
    const int nw = E_NUM * I_DIM * H_DIM;
    split_kernel<<<nx / 1024, 256>>>(x, 0, nx);
    split_kernel<<<nw / 1024, 256>>>(w1, 1, nw);
    split_kernel<<<nw / 1024, 256>>>(w2, 2, nw);
    split_kernel<<<nw / 1024, 256>>>(w3, 3, nw);

    gate_kernel<<<T_TOK / 8, 256>>>(x, gw);
    offsets_kernel<<<1, 32>>>(out, out_size);

    ffn1_kernel<<<dim3(I_DIM / 64, T_TOK / 128, E_NUM), 256, F1_SMEM>>>();
    ffn2_kernel<<<dim3(H_DIM / 128, T_TOK / 128, E_NUM), 256, F2_SMEM>>>();
    combine_kernel<<<T_TOK, 256>>>(out);
}

// round 6
// speedup vs baseline: 4.0709x; 1.6188x over previous
#include <cuda_runtime.h>
#include <cuda_fp16.h>
#include <math.h>
#include <stdint.h>

#define T_TOK 8192
#define H_DIM 1024
#define E_NUM 8
#define I_DIM 2048
#define NROW  (T_TOK * 2)

// ---------------- device-global scratch -------------------------------------
__device__ int   d_cnt[E_NUM];
__device__ float d_psum[E_NUM];
__device__ int   d_off[E_NUM];
__device__ int   d_tok[E_NUM * T_TOK];
__device__ float d_cw [E_NUM * T_TOK];
__device__ int   d_slot[T_TOK * 2];

__device__ __half g_xh[(size_t)T_TOK * H_DIM];
__device__ __half g_xl[(size_t)T_TOK * H_DIM];
__device__ __half g_w1h[(size_t)E_NUM * I_DIM * H_DIM];
__device__ __half g_w3h[(size_t)E_NUM * I_DIM * H_DIM];
__device__ __half g_w2h[(size_t)E_NUM * H_DIM * I_DIM];
__device__ __half g_hidh[(size_t)NROW * I_DIM];
__device__ __half g_hidl[(size_t)NROW * I_DIM];
__device__ float  g_y[(size_t)NROW * H_DIM];

// ---------------- PTX helpers (baseline ISA only) ----------------------------
__device__ __forceinline__ uint32_t smem_u32(const void* p) {
    uint32_t r;
    asm("{ .reg .u64 t; cvta.to.shared.u64 t, %1; cvt.u32.u64 %0, t; }"
        : "=r"(r) : "l"(p));
    return r;
}
__device__ __forceinline__ void cp16(uint32_t saddr, const void* gaddr) {
    asm volatile("cp.async.cg.shared.global [%0], [%1], 16;"
                 :: "r"(saddr), "l"(gaddr));
}
__device__ __forceinline__ void cp_commit() {
    asm volatile("cp.async.commit_group;");
}
template <int N> __device__ __forceinline__ void cp_wait() {
    asm volatile("cp.async.wait_group %0;" :: "n"(N));
}
__device__ __forceinline__ void ldsm4(uint32_t* r, uint32_t addr) {
    asm volatile("ldmatrix.sync.aligned.m8n8.x4.shared.b16 {%0,%1,%2,%3}, [%4];"
                 : "=r"(r[0]), "=r"(r[1]), "=r"(r[2]), "=r"(r[3]) : "r"(addr));
}
__device__ __forceinline__ void mma16816(float* d, const uint32_t* a,
                                         const uint32_t* b) {
    asm volatile(
        "mma.sync.aligned.m16n8k16.row.col.f32.f16.f16.f32 "
        "{%0,%1,%2,%3}, {%4,%5,%6,%7}, {%8,%9}, {%0,%1,%2,%3};"
        : "+f"(d[0]), "+f"(d[1]), "+f"(d[2]), "+f"(d[3])
        : "r"(a[0]), "r"(a[1]), "r"(a[2]), "r"(a[3]), "r"(b[0]), "r"(b[1]));
}
// swizzled address inside a [128 rows][64B] tile: conflict-free for ldmatrix+STS
__device__ __forceinline__ uint32_t tile_addr(uint32_t base, int row, int chunk) {
    return base + row * 64 + ((chunk ^ ((row >> 1) & 3)) << 4);
}
__device__ __forceinline__ uint32_t pack_h2(__half a, __half b) {
    __half2 t = __halves2half2(a, b);
    return *reinterpret_cast<uint32_t*>(&t);
}

// ---------------- small kernels ----------------------------------------------
__global__ void zero_kernel() {
    int i = threadIdx.x;
    if (i < E_NUM) { d_cnt[i] = 0; d_psum[i] = 0.f; }
}

// x -> 2-digit fp16 (hi + residual lo)
__global__ void split_x_kernel(const float* __restrict__ src, int n) {
    int i = (blockIdx.x * blockDim.x + threadIdx.x) * 4;
    if (i >= n) return;
    float4 v = *(const float4*)(src + i);
    __half hx = __float2half(v.x), hy = __float2half(v.y);
    __half hz = __float2half(v.z), hw = __float2half(v.w);
    __half lx = __float2half(v.x - __half2float(hx));
    __half ly = __float2half(v.y - __half2float(hy));
    __half lz = __float2half(v.z - __half2float(hz));
    __half lw = __float2half(v.w - __half2float(hw));
    uint2 H, L;
    H.x = pack_h2(hx, hy); H.y = pack_h2(hz, hw);
    L.x = pack_h2(lx, ly); L.y = pack_h2(lz, lw);
    *(uint2*)(g_xh + i) = H;
    *(uint2*)(g_xl + i) = L;
}

// weights -> single fp16 digit
__global__ void cvt_w_kernel(const float* __restrict__ src, int which, int n) {
    __half* dst = (which == 1) ? g_w1h : (which == 2) ? g_w2h : g_w3h;
    int i = (blockIdx.x * blockDim.x + threadIdx.x) * 4;
    if (i >= n) return;
    float4 v = *(const float4*)(src + i);
    uint2 H;
    H.x = pack_h2(__float2half(v.x), __float2half(v.y));
    H.y = pack_h2(__float2half(v.z), __float2half(v.w));
    *(uint2*)(dst + i) = H;
}

__global__ void gate_kernel(const float* __restrict__ x,
                            const float* __restrict__ gw) {
    int tok  = (blockIdx.x * blockDim.x + threadIdx.x) >> 5;
    int lane = threadIdx.x & 31;
    int wib  = threadIdx.x >> 5;
    __shared__ float sprob[8][E_NUM];

    float acc[E_NUM];
#pragma unroll
    for (int e = 0; e < E_NUM; e++) acc[e] = 0.f;
    const float* xr = x + (size_t)tok * H_DIM;
    for (int h = lane; h < H_DIM; h += 32) {
        float xv = xr[h];
#pragma unroll
        for (int e = 0; e < E_NUM; e++)
            acc[e] = fmaf(xv, gw[e * H_DIM + h], acc[e]);
    }
#pragma unroll
    for (int e = 0; e < E_NUM; e++)
#pragma unroll
        for (int o = 16; o > 0; o >>= 1)
            acc[e] += __shfl_xor_sync(0xffffffffu, acc[e], o);

    if (lane == 0) {
        float mx = acc[0];
#pragma unroll
        for (int e = 1; e < E_NUM; e++) mx = fmaxf(mx, acc[e]);
        float p[E_NUM], s = 0.f;
#pragma unroll
        for (int e = 0; e < E_NUM; e++) { p[e] = expf(acc[e] - mx); s += p[e]; }
        float inv = 1.f / s;
#pragma unroll
        for (int e = 0; e < E_NUM; e++) { p[e] *= inv; sprob[wib][e] = p[e]; }

        int i0 = 0; float v0 = p[0];
#pragma unroll
        for (int e = 1; e < E_NUM; e++) if (p[e] > v0) { v0 = p[e]; i0 = e; }
        int i1 = -1; float v1 = -1.f;
#pragma unroll
        for (int e = 0; e < E_NUM; e++)
            if (e != i0 && p[e] > v1) { v1 = p[e]; i1 = e; }

        float wn  = 1.f / (v0 + v1 + 1e-6f);
        int p0 = atomicAdd(&d_cnt[i0], 1);
        d_tok[i0 * T_TOK + p0] = tok;  d_cw[i0 * T_TOK + p0] = v0 * wn;
        d_slot[tok * 2 + 0] = i0 * T_TOK + p0;
        int p1 = atomicAdd(&d_cnt[i1], 1);
        d_tok[i1 * T_TOK + p1] = tok;  d_cw[i1 * T_TOK + p1] = v1 * wn;
        d_slot[tok * 2 + 1] = i1 * T_TOK + p1;
    }
    __syncthreads();
    if (threadIdx.x < E_NUM) {
        float s = 0.f;
#pragma unroll
        for (int w = 0; w < 8; w++) s += sprob[w][threadIdx.x];
        atomicAdd(&d_psum[threadIdx.x], s);
    }
}

__global__ void offsets_kernel(float* out, int out_size) {
    if (threadIdx.x == 0) {
        int off = 0; float aux = 0.f;
        for (int e = 0; e < E_NUM; e++) {
            d_off[e] = off;
            off += d_cnt[e];
            aux += ((float)d_cnt[e] / (float)T_TOK) * (d_psum[e] / (float)T_TOK);
        }
        aux *= (float)E_NUM;
        if (out_size > T_TOK * H_DIM) out[T_TOK * H_DIM] = aux;
    }
}

// ---------------- GEMM tile constants ----------------------------------------
// stage (24 KB): Ah[128][64B], Al[128][64B], Bh[128][64B]. 4 stages = 96 KB.
#define TS_AH 0
#define TS_AL 8192
#define TS_BH 16384
#define STAGE 24576
#define NSTAGE 4
#define EPI_STRIDE 68
#define F1_SMEM (NSTAGE * STAGE)   // 98304; epilogue (69632 B) aliases stages
#define F2_SMEM (NSTAGE * STAGE)

// ---------------- FFN1: h = silu(x w1^T) * (x w3^T) --------------------------
// block tile: M=128 routed rows, N=64 intermediate cols for both w1 & w3.
// Bh smem rows 0-63 = w1h[n0..], 64-127 = w3h[n0..]. 8 warps (wM 0-1)x(wN 0-3).
__global__ void __launch_bounds__(256, 2)
ffn1_kernel() {
    extern __shared__ char smem[];
    __shared__ int stok[128];
    const int e   = blockIdx.z;
    const int cnt = d_cnt[e];
    const int m0  = blockIdx.y * 128;
    if (m0 >= cnt) return;
    const int n0  = blockIdx.x * 64;

    const uint32_t sb = smem_u32(smem);
    const int tid = threadIdx.x, lane = tid & 31, wid = tid >> 5;
    const int wM = wid >> 2, wN = wid & 3;

    if (tid < 128) stok[tid] = (m0 + tid < cnt) ? d_tok[e * T_TOK + m0 + tid] : 0;
    __syncthreads();

    auto load_stage = [&](int k, int s) {
        const int k0 = k * 32;
        const uint32_t st = sb + s * STAGE;
#pragma unroll
        for (int t = 0; t < 6; t++) {
            int i = tid + t * 256;
            int region = i >> 9;          // 0 Ah, 1 Al, 2 Bh
            int idx = i & 511;
            int row = idx >> 2, c = idx & 3;
            uint32_t dst = tile_addr(st + region * 8192, row, c);
            if (region < 2) {
                const __half* src = region ? g_xl : g_xh;
                cp16(dst, src + (size_t)stok[row] * H_DIM + k0 + c * 8);
            } else {
                const __half* src = (row < 64) ? g_w1h : g_w3h;
                int r = row & 63;
                cp16(dst, src + ((size_t)e * I_DIM + n0 + r) * H_DIM + k0 + c * 8);
            }
        }
    };

    float acc[4][4][4];
#pragma unroll
    for (int mt = 0; mt < 4; mt++)
#pragma unroll
        for (int nt = 0; nt < 4; nt++)
#pragma unroll
            for (int q = 0; q < 4; q++) acc[mt][nt][q] = 0.f;

    const int NK = H_DIM / 32;
    load_stage(0, 0); cp_commit();
    load_stage(1, 1); cp_commit();
    load_stage(2, 2); cp_commit();

    for (int k = 0; k < NK; k++) {
        cp_wait<2>();
        __syncthreads();
        const uint32_t st = sb + (k & 3) * STAGE;
#pragma unroll
        for (int ks = 0; ks < 2; ks++) {
            const int cb = ks * 2 + (lane >> 4);
            uint32_t ah[4][4], al[4][4], bh[2][4];
#pragma unroll
            for (int mt = 0; mt < 4; mt++) {
                int row = wM * 64 + mt * 16 + (lane & 15);
                ldsm4(ah[mt], tile_addr(st + TS_AH, row, cb));
                ldsm4(al[mt], tile_addr(st + TS_AL, row, cb));
            }
#pragma unroll
            for (int p = 0; p < 2; p++) {
                int row = wN * 32 + p * 16 + (lane & 15);
                ldsm4(bh[p], tile_addr(st + TS_BH, row, cb));
            }
#pragma unroll
            for (int mt = 0; mt < 4; mt++)
#pragma unroll
                for (int nt = 0; nt < 4; nt++) {
                    int p = nt >> 1, o = nt & 1;
                    uint32_t b2[2] = {bh[p][o], bh[p][o + 2]};
                    mma16816(acc[mt][nt], ah[mt], b2);
                    mma16816(acc[mt][nt], al[mt], b2);
                }
        }
        if (k + 3 < NK) load_stage(k + 3, (k + 3) & 3);
        cp_commit();
    }
    __syncthreads();   // before epilogue aliases stage smem

    // epilogue: stash g/u in smem, combine, split to fp16 hi/lo
    float* Sg = (float*)smem;
    float* Su = Sg + 128 * EPI_STRIDE;
    float* Sacc = (wN < 2) ? Sg : Su;
    const int ncb = (wN & 1) * 32;
#pragma unroll
    for (int mt = 0; mt < 4; mt++) {
        int row = wM * 64 + mt * 16 + (lane >> 2);
#pragma unroll
        for (int nt = 0; nt < 4; nt++) {
            int col = ncb + nt * 8 + (lane & 3) * 2;
            Sacc[row * EPI_STRIDE + col]     = acc[mt][nt][0];
            Sacc[row * EPI_STRIDE + col + 1] = acc[mt][nt][1];
            Sacc[(row + 8) * EPI_STRIDE + col]     = acc[mt][nt][2];
            Sacc[(row + 8) * EPI_STRIDE + col + 1] = acc[mt][nt][3];
        }
    }
    __syncthreads();

    const int base = d_off[e];
    for (int idx = tid; idx < 128 * 32; idx += 256) {
        int m = idx >> 5;
        if (m0 + m >= cnt) continue;
        int c = (idx & 31) * 2;
        float g0 = Sg[m * EPI_STRIDE + c], g1 = Sg[m * EPI_STRIDE + c + 1];
        float u0 = Su[m * EPI_STRIDE + c], u1 = Su[m * EPI_STRIDE + c + 1];
        float h0 = (g0 / (1.f + expf(-g0))) * u0;
        float h1 = (g1 / (1.f + expf(-g1))) * u1;
        __half h0h = __float2half(h0);
        __half h1h = __float2half(h1);
        __half l0h = __float2half(h0 - __half2float(h0h));
        __half l1h = __float2half(h1 - __half2float(h1h));
        size_t gi = (size_t)(base + m0 + m) * I_DIM + n0 + c;
        *(uint32_t*)(g_hidh + gi) = pack_h2(h0h, h1h);
        *(uint32_t*)(g_hidl + gi) = pack_h2(l0h, l1h);
    }
}

// ---------------- FFN2: y[slot] = cw * (hidden w2^T) -------------------------
// block tile M=128, N=128 (H cols). 8 warps (wM 0-1)x(wN 0-3), 64x32 each.
__global__ void __launch_bounds__(256, 2)
ffn2_kernel() {
    extern __shared__ char smem[];
    __shared__ float scw[128];
    const int e   = blockIdx.z;
    const int cnt = d_cnt[e];
    const int m0  = blockIdx.y * 128;
    if (m0 >= cnt) return;
    const int n0  = blockIdx.x * 128;
    const int base = d_off[e];

    const uint32_t sb = smem_u32(smem);
    const int tid = threadIdx.x, lane = tid & 31, wid = tid >> 5;
    const int wM = wid >> 2, wN = wid & 3;

    if (tid < 128)
        scw[tid] = (m0 + tid < cnt) ? d_cw[e * T_TOK + m0 + tid] : 0.f;
    __syncthreads();

    auto load_stage = [&](int k, int s) {
        const int k0 = k * 32;
        const uint32_t st = sb + s * STAGE;
#pragma unroll
        for (int t = 0; t < 6; t++) {
            int i = tid + t * 256;
            int region = i >> 9;          // 0 Ah, 1 Al, 2 Bh
            int idx = i & 511;
            int row = idx >> 2, c = idx & 3;
            uint32_t dst = tile_addr(st + region * 8192, row, c);
            if (region < 2) {
                const __half* src = region ? g_hidl : g_hidh;
                int m = m0 + row;
                size_t gr = (size_t)(base + ((m < cnt) ? m : 0));
                cp16(dst, src + gr * I_DIM + k0 + c * 8);
            } else {
                cp16(dst, g_w2h + ((size_t)e * H_DIM + n0 + row) * I_DIM + k0 + c * 8);
            }
        }
    };

    float acc[4][4][4];
#pragma unroll
    for (int mt = 0; mt < 4; mt++)
#pragma unroll
        for (int nt = 0; nt < 4; nt++)
#pragma unroll
            for (int q = 0; q < 4; q++) acc[mt][nt][q] = 0.f;

    const int NK = I_DIM / 32;
    load_stage(0, 0); cp_commit();
    load_stage(1, 1); cp_commit();
    load_stage(2, 2); cp_commit();

    for (int k = 0; k < NK; k++) {
        cp_wait<2>();
        __syncthreads();
        const uint32_t st = sb + (k & 3) * STAGE;
#pragma unroll
        for (int ks = 0; ks < 2; ks++) {
            const int cb = ks * 2 + (lane >> 4);
            uint32_t ah[4][4], al[4][4], bh[2][4];
#pragma unroll
            for (int mt = 0; mt < 4; mt++) {
                int row = wM * 64 + mt * 16 + (lane & 15);
                ldsm4(ah[mt], tile_addr(st + TS_AH, row, cb));
                ldsm4(al[mt], tile_addr(st + TS_AL, row, cb));
            }
#pragma unroll
            for (int p = 0; p < 2; p++) {
                int row = wN * 32 + p * 16 + (lane & 15);
                ldsm4(bh[p], tile_addr(st + TS_BH, row, cb));
            }
#pragma unroll
            for (int mt = 0; mt < 4; mt++)
#pragma unroll
                for (int nt = 0; nt < 4; nt++) {
                    int p = nt >> 1, o = nt & 1;
                    uint32_t b2[2] = {bh[p][o], bh[p][o + 2]};
                    mma16816(acc[mt][nt], ah[mt], b2);
                    mma16816(acc[mt][nt], al[mt], b2);
                }
        }
        if (k + 3 < NK) load_stage(k + 3, (k + 3) & 3);
        cp_commit();
    }

    // epilogue: scale by cw, store f32 rows to compact y
#pragma unroll
    for (int mt = 0; mt < 4; mt++) {
        int r0 = wM * 64 + mt * 16 + (lane >> 2);
        int r1 = r0 + 8;
        bool v0 = (m0 + r0 < cnt), v1 = (m0 + r1 < cnt);
        float c0 = scw[r0], c1 = scw[r1];
        float* y0 = g_y + (size_t)(base + m0 + r0) * H_DIM + n0;
        float* y1 = g_y + (size_t)(base + m0 + r1) * H_DIM + n0;
#pragma unroll
        for (int nt = 0; nt < 4; nt++) {
            int col = wN * 32 + nt * 8 + (lane & 3) * 2;
            if (v0) *(float2*)(y0 + col) =
                make_float2(c0 * acc[mt][nt][0], c0 * acc[mt][nt][1]);
            if (v1) *(float2*)(y1 + col) =
                make_float2(c1 * acc[mt][nt][2], c1 * acc[mt][nt][3]);
        }
    }
}

// ---------------- combine ----------------------------------------------------
__global__ void combine_kernel(float* __restrict__ out) {
    const int tok = blockIdx.x;
    const int c = threadIdx.x * 4;
    int s0 = d_slot[tok * 2], s1 = d_slot[tok * 2 + 1];
    int r0 = d_off[s0 >> 13] + (s0 & (T_TOK - 1));
    int r1 = d_off[s1 >> 13] + (s1 & (T_TOK - 1));
    float4 a = *(const float4*)(g_y + (size_t)r0 * H_DIM + c);
    float4 b = *(const float4*)(g_y + (size_t)r1 * H_DIM + c);
    float4 o;
    o.x = a.x + b.x; o.y = a.y + b.y; o.z = a.z + b.z; o.w = a.w + b.w;
    *(float4*)(out + (size_t)tok * H_DIM + c) = o;
}

// ---------------- launch -----------------------------------------------------
extern "C" void kernel_launch(void* const* d_in, const int* in_sizes, int n_in,
                              void* d_out, int out_size) {
    const float* x    = (const float*)d_in[0];
    const float* gw   = (const float*)d_in[1];
    const float* w1   = (const float*)d_in[2];
    const float* w2   = (const float*)d_in[3];
    const float* w3   = (const float*)d_in[4];
    float* out = (float*)d_out;

    cudaFuncSetAttribute(ffn1_kernel, cudaFuncAttributeMaxDynamicSharedMemorySize, F1_SMEM);
    cudaFuncSetAttribute(ffn2_kernel, cudaFuncAttributeMaxDynamicSharedMemorySize, F2_SMEM);

    cudaMemsetAsync(d_out, 0, (size_t)out_size * sizeof(float), 0);
    zero_kernel<<<1, 32>>>();

    const int nx = T_TOK * H_DIM;
    const int nw = E_NUM * I_DIM * H_DIM;
    split_x_kernel<<<nx / 1024, 256>>>(x, nx);
    cvt_w_kernel<<<nw / 1024, 256>>>(w1, 1, nw);
    cvt_w_kernel<<<nw / 1024, 256>>>(w2, 2, nw);
    cvt_w_kernel<<<nw / 1024, 256>>>(w3, 3, nw);

    gate_kernel<<<T_TOK / 8, 256>>>(x, gw);
    offsets_kernel<<<1, 32>>>(out, out_size);

    ffn1_kernel<<<dim3(I_DIM / 64, T_TOK / 128, E_NUM), 256, F1_SMEM>>>();
    ffn2_kernel<<<dim3(H_DIM / 128, T_TOK / 128, E_NUM), 256, F2_SMEM>>>();
    combine_kernel<<<T_TOK, 256>>>(out);
}

// round 7
// speedup vs baseline: 6.8687x; 1.6873x over previous
#include <cuda_runtime.h>
#include <cuda_fp16.h>
#include <math.h>
#include <stdint.h>

#define T_TOK 8192
#define H_DIM 1024
#define E_NUM 8
#define I_DIM 2048
#define NROW  (T_TOK * 2)

// ---------------- device-global scratch -------------------------------------
__device__ int   d_cnt[E_NUM];
__device__ float d_psum[E_NUM];
__device__ int   d_off[E_NUM];
__device__ int   d_tok[E_NUM * T_TOK];
__device__ float d_cw [E_NUM * T_TOK];
__device__ int   d_slot[T_TOK * 2];

__device__ __half g_xh[(size_t)T_TOK * H_DIM];
__device__ __half g_w1h[(size_t)E_NUM * I_DIM * H_DIM];
__device__ __half g_w3h[(size_t)E_NUM * I_DIM * H_DIM];
__device__ __half g_w2h[(size_t)E_NUM * H_DIM * I_DIM];
__device__ __half g_hidh[(size_t)NROW * I_DIM];
__device__ float  g_y[(size_t)NROW * H_DIM];

// ---------------- PTX helpers (baseline ISA only) ----------------------------
__device__ __forceinline__ uint32_t smem_u32(const void* p) {
    uint32_t r;
    asm("{ .reg .u64 t; cvta.to.shared.u64 t, %1; cvt.u32.u64 %0, t; }"
        : "=r"(r) : "l"(p));
    return r;
}
__device__ __forceinline__ void cp16(uint32_t saddr, const void* gaddr) {
    asm volatile("cp.async.cg.shared.global [%0], [%1], 16;"
                 :: "r"(saddr), "l"(gaddr));
}
__device__ __forceinline__ void cp_commit() {
    asm volatile("cp.async.commit_group;");
}
template <int N> __device__ __forceinline__ void cp_wait() {
    asm volatile("cp.async.wait_group %0;" :: "n"(N));
}
__device__ __forceinline__ void ldsm4(uint32_t* r, uint32_t addr) {
    asm volatile("ldmatrix.sync.aligned.m8n8.x4.shared.b16 {%0,%1,%2,%3}, [%4];"
                 : "=r"(r[0]), "=r"(r[1]), "=r"(r[2]), "=r"(r[3]) : "r"(addr));
}
__device__ __forceinline__ void mma16816(float* d, const uint32_t* a,
                                         const uint32_t* b) {
    asm volatile(
        "mma.sync.aligned.m16n8k16.row.col.f32.f16.f16.f32 "
        "{%0,%1,%2,%3}, {%4,%5,%6,%7}, {%8,%9}, {%0,%1,%2,%3};"
        : "+f"(d[0]), "+f"(d[1]), "+f"(d[2]), "+f"(d[3])
        : "r"(a[0]), "r"(a[1]), "r"(a[2]), "r"(a[3]), "r"(b[0]), "r"(b[1]));
}
// swizzled address inside a [128 rows][64B] tile: conflict-free for ldmatrix+STS
__device__ __forceinline__ uint32_t tile_addr(uint32_t base, int row, int chunk) {
    return base + row * 64 + ((chunk ^ ((row >> 1) & 3)) << 4);
}
__device__ __forceinline__ uint32_t pack_h2(__half a, __half b) {
    __half2 t = __halves2half2(a, b);
    return *reinterpret_cast<uint32_t*>(&t);
}

// ---------------- small kernels ----------------------------------------------
__global__ void zero_kernel() {
    int i = threadIdx.x;
    if (i < E_NUM) { d_cnt[i] = 0; d_psum[i] = 0.f; }
}

// fp32 -> single fp16 digit (x and weights)
__global__ void cvt_kernel(const float* __restrict__ src, int which, int n) {
    __half* dst = (which == 0) ? g_xh : (which == 1) ? g_w1h
                : (which == 2) ? g_w2h : g_w3h;
    int i = (blockIdx.x * blockDim.x + threadIdx.x) * 4;
    if (i >= n) return;
    float4 v = *(const float4*)(src + i);
    uint2 H;
    H.x = pack_h2(__float2half(v.x), __float2half(v.y));
    H.y = pack_h2(__float2half(v.z), __float2half(v.w));
    *(uint2*)(dst + i) = H;
}

__global__ void gate_kernel(const float* __restrict__ x,
                            const float* __restrict__ gw) {
    int tok  = (blockIdx.x * blockDim.x + threadIdx.x) >> 5;
    int lane = threadIdx.x & 31;
    int wib  = threadIdx.x >> 5;
    __shared__ float sprob[8][E_NUM];

    float acc[E_NUM];
#pragma unroll
    for (int e = 0; e < E_NUM; e++) acc[e] = 0.f;
    const float* xr = x + (size_t)tok * H_DIM;
    for (int h = lane; h < H_DIM; h += 32) {
        float xv = xr[h];
#pragma unroll
        for (int e = 0; e < E_NUM; e++)
            acc[e] = fmaf(xv, gw[e * H_DIM + h], acc[e]);
    }
#pragma unroll
    for (int e = 0; e < E_NUM; e++)
#pragma unroll
        for (int o = 16; o > 0; o >>= 1)
            acc[e] += __shfl_xor_sync(0xffffffffu, acc[e], o);

    if (lane == 0) {
        float mx = acc[0];
#pragma unroll
        for (int e = 1; e < E_NUM; e++) mx = fmaxf(mx, acc[e]);
        float p[E_NUM], s = 0.f;
#pragma unroll
        for (int e = 0; e < E_NUM; e++) { p[e] = expf(acc[e] - mx); s += p[e]; }
        float inv = 1.f / s;
#pragma unroll
        for (int e = 0; e < E_NUM; e++) { p[e] *= inv; sprob[wib][e] = p[e]; }

        int i0 = 0; float v0 = p[0];
#pragma unroll
        for (int e = 1; e < E_NUM; e++) if (p[e] > v0) { v0 = p[e]; i0 = e; }
        int i1 = -1; float v1 = -1.f;
#pragma unroll
        for (int e = 0; e < E_NUM; e++)
            if (e != i0 && p[e] > v1) { v1 = p[e]; i1 = e; }

        float wn  = 1.f / (v0 + v1 + 1e-6f);
        int p0 = atomicAdd(&d_cnt[i0], 1);
        d_tok[i0 * T_TOK + p0] = tok;  d_cw[i0 * T_TOK + p0] = v0 * wn;
        d_slot[tok * 2 + 0] = i0 * T_TOK + p0;
        int p1 = atomicAdd(&d_cnt[i1], 1);
        d_tok[i1 * T_TOK + p1] = tok;  d_cw[i1 * T_TOK + p1] = v1 * wn;
        d_slot[tok * 2 + 1] = i1 * T_TOK + p1;
    }
    __syncthreads();
    if (threadIdx.x < E_NUM) {
        float s = 0.f;
#pragma unroll
        for (int w = 0; w < 8; w++) s += sprob[w][threadIdx.x];
        atomicAdd(&d_psum[threadIdx.x], s);
    }
}

__global__ void offsets_kernel(float* out, int out_size) {
    if (threadIdx.x == 0) {
        int off = 0; float aux = 0.f;
        for (int e = 0; e < E_NUM; e++) {
            d_off[e] = off;
            off += d_cnt[e];
            aux += ((float)d_cnt[e] / (float)T_TOK) * (d_psum[e] / (float)T_TOK);
        }
        aux *= (float)E_NUM;
        if (out_size > T_TOK * H_DIM) out[T_TOK * H_DIM] = aux;
    }
}

// ---------------- GEMM tile constants ----------------------------------------
// stage (16 KB): A[128][64B], B[128][64B]. 4 stages = 64 KB.
#define TS_A 0
#define TS_B 8192
#define STAGE 16384
#define NSTAGE 4
#define EPI_STRIDE 68
#define F1_SMEM (NSTAGE * STAGE + 8192)  // 73728 >= epilogue 69632
#define F2_SMEM (NSTAGE * STAGE)

// ---------------- FFN1: h = silu(x w1^T) * (x w3^T) --------------------------
// block tile: M=128 routed rows, N=64 intermediate cols for both w1 & w3.
// B smem rows 0-63 = w1h[n0..], 64-127 = w3h[n0..]. 8 warps (wM 0-1)x(wN 0-3).
__global__ void __launch_bounds__(256, 2)
ffn1_kernel() {
    extern __shared__ char smem[];
    __shared__ int stok[128];
    const int e   = blockIdx.z;
    const int cnt = d_cnt[e];
    const int m0  = blockIdx.y * 128;
    if (m0 >= cnt) return;
    const int n0  = blockIdx.x * 64;

    const uint32_t sb = smem_u32(smem);
    const int tid = threadIdx.x, lane = tid & 31, wid = tid >> 5;
    const int wM = wid >> 2, wN = wid & 3;

    if (tid < 128) stok[tid] = (m0 + tid < cnt) ? d_tok[e * T_TOK + m0 + tid] : 0;
    __syncthreads();

    auto load_stage = [&](int k, int s) {
        const int k0 = k * 32;
        const uint32_t st = sb + s * STAGE;
#pragma unroll
        for (int t = 0; t < 4; t++) {
            int i = tid + t * 256;
            int region = i >> 9;          // 0 A, 1 B
            int idx = i & 511;
            int row = idx >> 2, c = idx & 3;
            uint32_t dst = tile_addr(st + region * 8192, row, c);
            if (region == 0) {
                cp16(dst, g_xh + (size_t)stok[row] * H_DIM + k0 + c * 8);
            } else {
                const __half* src = (row < 64) ? g_w1h : g_w3h;
                int r = row & 63;
                cp16(dst, src + ((size_t)e * I_DIM + n0 + r) * H_DIM + k0 + c * 8);
            }
        }
    };

    float acc[4][4][4];
#pragma unroll
    for (int mt = 0; mt < 4; mt++)
#pragma unroll
        for (int nt = 0; nt < 4; nt++)
#pragma unroll
            for (int q = 0; q < 4; q++) acc[mt][nt][q] = 0.f;

    const int NK = H_DIM / 32;
    load_stage(0, 0); cp_commit();
    load_stage(1, 1); cp_commit();
    load_stage(2, 2); cp_commit();

    for (int k = 0; k < NK; k++) {
        cp_wait<2>();
        __syncthreads();
        const uint32_t st = sb + (k & 3) * STAGE;
#pragma unroll
        for (int ks = 0; ks < 2; ks++) {
            const int cb = ks * 2 + (lane >> 4);
            uint32_t a[4][4], bh[2][4];
#pragma unroll
            for (int mt = 0; mt < 4; mt++) {
                int row = wM * 64 + mt * 16 + (lane & 15);
                ldsm4(a[mt], tile_addr(st + TS_A, row, cb));
            }
#pragma unroll
            for (int p = 0; p < 2; p++) {
                int row = wN * 32 + p * 16 + (lane & 15);
                ldsm4(bh[p], tile_addr(st + TS_B, row, cb));
            }
#pragma unroll
            for (int mt = 0; mt < 4; mt++)
#pragma unroll
                for (int nt = 0; nt < 4; nt++) {
                    int p = nt >> 1, o = nt & 1;
                    uint32_t b2[2] = {bh[p][o], bh[p][o + 2]};
                    mma16816(acc[mt][nt], a[mt], b2);
                }
        }
        if (k + 3 < NK) load_stage(k + 3, (k + 3) & 3);
        cp_commit();
    }
    __syncthreads();   // before epilogue aliases stage smem

    // epilogue: stash g/u in smem, combine, convert to fp16
    float* Sg = (float*)smem;
    float* Su = Sg + 128 * EPI_STRIDE;
    float* Sacc = (wN < 2) ? Sg : Su;
    const int ncb = (wN & 1) * 32;
#pragma unroll
    for (int mt = 0; mt < 4; mt++) {
        int row = wM * 64 + mt * 16 + (lane >> 2);
#pragma unroll
        for (int nt = 0; nt < 4; nt++) {
            int col = ncb + nt * 8 + (lane & 3) * 2;
            Sacc[row * EPI_STRIDE + col]     = acc[mt][nt][0];
            Sacc[row * EPI_STRIDE + col + 1] = acc[mt][nt][1];
            Sacc[(row + 8) * EPI_STRIDE + col]     = acc[mt][nt][2];
            Sacc[(row + 8) * EPI_STRIDE + col + 1] = acc[mt][nt][3];
        }
    }
    __syncthreads();

    const int base = d_off[e];
    for (int idx = tid; idx < 128 * 32; idx += 256) {
        int m = idx >> 5;
        if (m0 + m >= cnt) continue;
        int c = (idx & 31) * 2;
        float g0 = Sg[m * EPI_STRIDE + c], g1 = Sg[m * EPI_STRIDE + c + 1];
        float u0 = Su[m * EPI_STRIDE + c], u1 = Su[m * EPI_STRIDE + c + 1];
        float h0 = (g0 / (1.f + expf(-g0))) * u0;
        float h1 = (g1 / (1.f + expf(-g1))) * u1;
        size_t gi = (size_t)(base + m0 + m) * I_DIM + n0 + c;
        *(uint32_t*)(g_hidh + gi) = pack_h2(__float2half(h0), __float2half(h1));
    }
}

// ---------------- FFN2: y[slot] = cw * (hidden w2^T) -------------------------
// block tile M=128, N=128 (H cols). 8 warps (wM 0-1)x(wN 0-3), 64x32 each.
__global__ void __launch_bounds__(256, 2)
ffn2_kernel() {
    extern __shared__ char smem[];
    __shared__ float scw[128];
    const int e   = blockIdx.z;
    const int cnt = d_cnt[e];
    const int m0  = blockIdx.y * 128;
    if (m0 >= cnt) return;
    const int n0  = blockIdx.x * 128;
    const int base = d_off[e];

    const uint32_t sb = smem_u32(smem);
    const int tid = threadIdx.x, lane = tid & 31, wid = tid >> 5;
    const int wM = wid >> 2, wN = wid & 3;

    if (tid < 128)
        scw[tid] = (m0 + tid < cnt) ? d_cw[e * T_TOK + m0 + tid] : 0.f;
    __syncthreads();

    auto load_stage = [&](int k, int s) {
        const int k0 = k * 32;
        const uint32_t st = sb + s * STAGE;
#pragma unroll
        for (int t = 0; t < 4; t++) {
            int i = tid + t * 256;
            int region = i >> 9;          // 0 A, 1 B
            int idx = i & 511;
            int row = idx >> 2, c = idx & 3;
            uint32_t dst = tile_addr(st + region * 8192, row, c);
            if (region == 0) {
                int m = m0 + row;
                size_t gr = (size_t)(base + ((m < cnt) ? m : 0));
                cp16(dst, g_hidh + gr * I_DIM + k0 + c * 8);
            } else {
                cp16(dst, g_w2h + ((size_t)e * H_DIM + n0 + row) * I_DIM + k0 + c * 8);
            }
        }
    };

    float acc[4][4][4];
#pragma unroll
    for (int mt = 0; mt < 4; mt++)
#pragma unroll
        for (int nt = 0; nt < 4; nt++)
#pragma unroll
            for (int q = 0; q < 4; q++) acc[mt][nt][q] = 0.f;

    const int NK = I_DIM / 32;
    load_stage(0, 0); cp_commit();
    load_stage(1, 1); cp_commit();
    load_stage(2, 2); cp_commit();

    for (int k = 0; k < NK; k++) {
        cp_wait<2>();
        __syncthreads();
        const uint32_t st = sb + (k & 3) * STAGE;
#pragma unroll
        for (int ks = 0; ks < 2; ks++) {
            const int cb = ks * 2 + (lane >> 4);
            uint32_t a[4][4], bh[2][4];
#pragma unroll
            for (int mt = 0; mt < 4; mt++) {
                int row = wM * 64 + mt * 16 + (lane & 15);
                ldsm4(a[mt], tile_addr(st + TS_A, row, cb));
            }
#pragma unroll
            for (int p = 0; p < 2; p++) {
                int row = wN * 32 + p * 16 + (lane & 15);
                ldsm4(bh[p], tile_addr(st + TS_B, row, cb));
            }
#pragma unroll
            for (int mt = 0; mt < 4; mt++)
#pragma unroll
                for (int nt = 0; nt < 4; nt++) {
                    int p = nt >> 1, o = nt & 1;
                    uint32_t b2[2] = {bh[p][o], bh[p][o + 2]};
                    mma16816(acc[mt][nt], a[mt], b2);
                }
        }
        if (k + 3 < NK) load_stage(k + 3, (k + 3) & 3);
        cp_commit();
    }

    // epilogue: scale by cw, store f32 rows to compact y
#pragma unroll
    for (int mt = 0; mt < 4; mt++) {
        int r0 = wM * 64 + mt * 16 + (lane >> 2);
        int r1 = r0 + 8;
        bool v0 = (m0 + r0 < cnt), v1 = (m0 + r1 < cnt);
        float c0 = scw[r0], c1 = scw[r1];
        float* y0 = g_y + (size_t)(base + m0 + r0) * H_DIM + n0;
        float* y1 = g_y + (size_t)(base + m0 + r1) * H_DIM + n0;
#pragma unroll
        for (int nt = 0; nt < 4; nt++) {
            int col = wN * 32 + nt * 8 + (lane & 3) * 2;
            if (v0) *(float2*)(y0 + col) =
                make_float2(c0 * acc[mt][nt][0], c0 * acc[mt][nt][1]);
            if (v1) *(float2*)(y1 + col) =
                make_float2(c1 * acc[mt][nt][2], c1 * acc[mt][nt][3]);
        }
    }
}

// ---------------- combine ----------------------------------------------------
__global__ void combine_kernel(float* __restrict__ out) {
    const int tok = blockIdx.x;
    const int c = threadIdx.x * 4;
    int s0 = d_slot[tok * 2], s1 = d_slot[tok * 2 + 1];
    int r0 = d_off[s0 >> 13] + (s0 & (T_TOK - 1));
    int r1 = d_off[s1 >> 13] + (s1 & (T_TOK - 1));
    float4 a = *(const float4*)(g_y + (size_t)r0 * H_DIM + c);
    float4 b = *(const float4*)(g_y + (size_t)r1 * H_DIM + c);
    float4 o;
    o.x = a.x + b.x; o.y = a.y + b.y; o.z = a.z + b.z; o.w = a.w + b.w;
    *(float4*)(out + (size_t)tok * H_DIM + c) = o;
}

// ---------------- launch -----------------------------------------------------
extern "C" void kernel_launch(void* const* d_in, const int* in_sizes, int n_in,
                              void* d_out, int out_size) {
    const float* x    = (const float*)d_in[0];
    const float* gw   = (const float*)d_in[1];
    const float* w1   = (const float*)d_in[2];
    const float* w2   = (const float*)d_in[3];
    const float* w3   = (const float*)d_in[4];
    float* out = (float*)d_out;

    cudaFuncSetAttribute(ffn1_kernel, cudaFuncAttributeMaxDynamicSharedMemorySize, F1_SMEM);
    cudaFuncSetAttribute(ffn2_kernel, cudaFuncAttributeMaxDynamicSharedMemorySize, F2_SMEM);

    cudaMemsetAsync(d_out, 0, (size_t)out_size * sizeof(float), 0);
    zero_kernel<<<1, 32>>>();

    const int nx = T_TOK * H_DIM;
    const int nw = E_NUM * I_DIM * H_DIM;
    cvt_kernel<<<nx / 1024, 256>>>(x, 0, nx);
    cvt_kernel<<<nw / 1024, 256>>>(w1, 1, nw);
    cvt_kernel<<<nw / 1024, 256>>>(w2, 2, nw);
    cvt_kernel<<<nw / 1024, 256>>>(w3, 3, nw);

    gate_kernel<<<T_TOK / 8, 256>>>(x, gw);
    offsets_kernel<<<1, 32>>>(out, out_size);

    ffn1_kernel<<<dim3(I_DIM / 64, T_TOK / 128, E_NUM), 256, F1_SMEM>>>();
    ffn2_kernel<<<dim3(H_DIM / 128, T_TOK / 128, E_NUM), 256, F2_SMEM>>>();
    combine_kernel<<<T_TOK, 256>>>(out);
}